// round 9
// baseline (speedup 1.0000x reference)
#include <cuda_runtime.h>
#include <cuda_fp16.h>
#include <cstdint>
#include <cstddef>

#define C   128
#define N0  20000
#define E1V 500000
#define E2V 500000
#define TV  500000

// ---------------- static device scratch (no allocations allowed) ----------------
__device__ __half g_y0h[(size_t)N0 * C];
__device__ __half g_y1h[(size_t)E1V * C];
__device__ __half g_y2h[(size_t)E2V * C];
__device__ float  g_a0[(size_t)N0 * C];
__device__ float  g_a1[(size_t)E1V * C];
__device__ float  g_a2[(size_t)E2V * C];
__device__ __half g_tmp [(size_t)E1V * C];   // f16 segment buffers
__device__ __half g_tmp2[(size_t)E1V * C];
__device__ __half g_tmp3[(size_t)E1V * C];

__device__ __forceinline__ void red4(float* p, float a, float b, float c, float d) {
    asm volatile("red.global.add.v4.f32 [%0], {%1,%2,%3,%4};"
                 :: "l"(p), "f"(a), "f"(b), "f"(c), "f"(d) : "memory");
}
// pack two f32 -> f16x2 (lo = first, hi = second)
__device__ __forceinline__ uint32_t pk(float lo, float hi) {
    uint32_t d;
    asm("cvt.rn.f16x2.f32 %0, %1, %2;" : "=r"(d) : "f"(hi), "f"(lo));
    return d;
}
// vector f16 reduction: 4 halves starting at p (8B aligned)
__device__ __forceinline__ void red2h(__half* p, float a, float b, float c, float d) {
    uint32_t lo = pk(a, b), hi = pk(c, d);
    asm volatile("red.global.add.noftz.v2.f16x2 [%0], {%1,%2};"
                 :: "l"(p), "r"(lo), "r"(hi) : "memory");
}
// read 4 consecutive f16 (cols lane*4..) of row as floats
__device__ __forceinline__ float4 ldy(const __half* y, int row, int lane) {
    uint2 u = *(const uint2*)(y + (size_t)row * C + lane * 4);
    __half2 h0 = *(__half2*)&u.x, h1 = *(__half2*)&u.y;
    float2 a = __half22float2(h0), b = __half22float2(h1);
    return make_float4(a.x, a.y, b.x, b.y);
}

// ---- f16 tile layout: 128 rows, 8 k16-groups of 8 f16x2 words, row stride 72 ----
#define ROWW 72
#define TWORDS (128 * ROWW)
__device__ __forceinline__ int widx(int r, int g, int p) { return r * ROWW + g * 8 + p; }

// LDG a 128x128 fp32 tile -> 16 packed f16x2 regs. Thread: row=tid>>2, q=tid&3.
template<bool ZEROA>
__device__ __forceinline__ void ldg_tile(const float* A, float* Az, int row0,
                                         int M, int tid, uint32_t* w)
{
    const int row = row0 + (tid >> 2), q = tid & 3;
    float4 f[8];
#pragma unroll
    for (int j = 0; j < 8; j++) f[j] = make_float4(0.f, 0.f, 0.f, 0.f);
    if (row < M) {
        const float4* g = (const float4*)(A + (size_t)row * C + q * 32);
#pragma unroll
        for (int j = 0; j < 8; j++) f[j] = g[j];
        if (ZEROA) {
            float4* z = (float4*)(Az + (size_t)row * C + q * 32);
#pragma unroll
            for (int j = 0; j < 8; j++) z[j] = make_float4(0.f, 0.f, 0.f, 0.f);
        }
    }
#pragma unroll
    for (int h = 0; h < 2; h++) {
        const float4 f0 = f[h * 4 + 0], f1 = f[h * 4 + 1];
        const float4 f2 = f[h * 4 + 2], f3 = f[h * 4 + 3];
        uint32_t* o = w + h * 8;
        o[0] = pk(f0.x, f0.y); o[1] = pk(f2.x, f2.y);
        o[2] = pk(f0.z, f0.w); o[3] = pk(f2.z, f2.w);
        o[4] = pk(f1.x, f1.y); o[5] = pk(f3.x, f3.y);
        o[6] = pk(f1.z, f1.w); o[7] = pk(f3.z, f3.w);
    }
}

// LDG a 128x128 f16 tile -> same packed layout (pure register permute, no cvt).
template<bool ZEROA>
__device__ __forceinline__ void ldg_tile_h(const __half* A, __half* Az, int row0,
                                           int M, int tid, uint32_t* w)
{
    const int row = row0 + (tid >> 2), q = tid & 3;
    uint32_t in[16];
#pragma unroll
    for (int j = 0; j < 16; j++) in[j] = 0;
    if (row < M) {
        const uint4* g = (const uint4*)(A + (size_t)row * C + q * 32);
#pragma unroll
        for (int j = 0; j < 4; j++) {
            uint4 v = g[j];
            in[j * 4 + 0] = v.x; in[j * 4 + 1] = v.y;
            in[j * 4 + 2] = v.z; in[j * 4 + 3] = v.w;
        }
        if (ZEROA) {
            uint4* z = (uint4*)(Az + (size_t)row * C + q * 32);
#pragma unroll
            for (int j = 0; j < 4; j++) z[j] = make_uint4(0, 0, 0, 0);
        }
    }
#pragma unroll
    for (int h = 0; h < 2; h++) {
        const uint32_t* i8 = in + h * 8;
        uint32_t* o = w + h * 8;
        o[0] = i8[0]; o[1] = i8[4]; o[2] = i8[1]; o[3] = i8[5];
        o[4] = i8[2]; o[5] = i8[6]; o[6] = i8[3]; o[7] = i8[7];
    }
}

__device__ __forceinline__ void sts_tile(uint32_t* buf, int tid, const uint32_t* w)
{
    const int row = tid >> 2, q = tid & 3;
    *(uint4*)(buf + widx(row, 2 * q,     0)) = make_uint4(w[0],  w[1],  w[2],  w[3]);
    *(uint4*)(buf + widx(row, 2 * q,     4)) = make_uint4(w[4],  w[5],  w[6],  w[7]);
    *(uint4*)(buf + widx(row, 2 * q + 1, 0)) = make_uint4(w[8],  w[9],  w[10], w[11]);
    *(uint4*)(buf + widx(row, 2 * q + 1, 4)) = make_uint4(w[12], w[13], w[14], w[15]);
}

__device__ __forceinline__ void mma_f16(const uint32_t* Ab, const uint32_t* Wb,
                                        int wm, int wn, int gid, int tig,
                                        float acc[2][4][4])
{
#pragma unroll
    for (int g = 0; g < 8; g++) {
        uint32_t af[2][4], bf[4][2];
#pragma unroll
        for (int t = 0; t < 2; t++) {
            const int rl = wm + t * 16 + gid;
            uint2 lo = *(const uint2*)(Ab + widx(rl,     g, tig * 2));
            uint2 hi = *(const uint2*)(Ab + widx(rl + 8, g, tig * 2));
            af[t][0] = lo.x; af[t][1] = hi.x; af[t][2] = lo.y; af[t][3] = hi.y;
        }
#pragma unroll
        for (int tb = 0; tb < 4; tb++) {
            const int n = wn + tb * 8 + gid;
            uint2 b = *(const uint2*)(Wb + widx(n, g, tig * 2));
            bf[tb][0] = b.x; bf[tb][1] = b.y;
        }
#pragma unroll
        for (int t = 0; t < 2; t++)
#pragma unroll
            for (int tb = 0; tb < 4; tb++)
                asm("mma.sync.aligned.m16n8k16.row.col.f32.f16.f16.f32 "
                    "{%0,%1,%2,%3}, {%4,%5,%6,%7}, {%8,%9}, {%0,%1,%2,%3};"
                    : "+f"(acc[t][tb][0]), "+f"(acc[t][tb][1]),
                      "+f"(acc[t][tb][2]), "+f"(acc[t][tb][3])
                    : "r"(af[t][0]), "r"(af[t][1]), "r"(af[t][2]), "r"(af[t][3]),
                      "r"(bf[tb][0]), "r"(bf[tb][1]));
    }
}

template<bool BIAS, bool RELU, bool ACC, bool RESID, bool OUTH>
__device__ __forceinline__ void epilogue(float acc[2][4][4], const float* bias,
                                         const float* R, void* CoutV, int r0,
                                         int wm, int wn, int gid, int tig, int M)
{
#pragma unroll
    for (int t = 0; t < 2; t++) {
        const int r = r0 + wm + t * 16 + gid;
#pragma unroll
        for (int tb = 0; tb < 4; tb++) {
            const int cc = wn + tb * 8 + tig * 2;
            float b0 = 0.f, b1 = 0.f;
            if (BIAS) { float2 bb = *(const float2*)(bias + cc); b0 = bb.x; b1 = bb.y; }
            float d0 = acc[t][tb][0] + b0, d1 = acc[t][tb][1] + b1;
            float d2 = acc[t][tb][2] + b0, d3 = acc[t][tb][3] + b1;
            if (RELU) {
                d0 = fmaxf(d0, 0.f); d1 = fmaxf(d1, 0.f);
                d2 = fmaxf(d2, 0.f); d3 = fmaxf(d3, 0.f);
            }
            if (OUTH) {
                __half* H = (__half*)CoutV;
                if (r < M)     *(uint32_t*)(H + (size_t)r * C + cc)       = pk(d0, d1);
                if (r + 8 < M) *(uint32_t*)(H + (size_t)(r + 8) * C + cc) = pk(d2, d3);
            } else {
                float* Cout = (float*)CoutV;
                if (r < M) {
                    float* p = Cout + (size_t)r * C + cc;
                    float2 v = make_float2(d0, d1);
                    if (ACC)   { float2 o = *(const float2*)p; v.x += o.x; v.y += o.y; }
                    if (RESID) { float2 o = *(const float2*)(R + (size_t)r * C + cc);
                                 v.x += o.x; v.y += o.y; }
                    *(float2*)p = v;
                }
                if (r + 8 < M) {
                    float* p = Cout + (size_t)(r + 8) * C + cc;
                    float2 v = make_float2(d2, d3);
                    if (ACC)   { float2 o = *(const float2*)p; v.x += o.x; v.y += o.y; }
                    if (RESID) { float2 o = *(const float2*)(R + (size_t)(r + 8) * C + cc);
                                 v.x += o.x; v.y += o.y; }
                    *(float2*)p = v;
                }
            }
        }
    }
}

// ======================= standalone persistent f16 GEMM ==========================
#define GEMM_SMEM (3 * TWORDS * 4)
template<bool BIAS, bool RELU, bool ACC, bool RESID, bool ZEROA, bool OUTH, bool AH>
__global__ __launch_bounds__(512, 1)
void tgemm(const void* __restrict__ A, const float* __restrict__ W,
           const float* __restrict__ bias, const float* __restrict__ R,
           void* __restrict__ Cout, void* __restrict__ Az, int M, int ntiles)
{
    extern __shared__ uint32_t sm[];
    uint32_t* Wf = sm;
    uint32_t* Ab[2] = { sm + TWORDS, sm + 2 * TWORDS };
    const int tid = threadIdx.x;
    const int lane = tid & 31, warp = tid >> 5;
    const int gid = lane >> 2, tig = lane & 3;
    const int wm = (warp >> 2) * 32, wn = (warp & 3) * 32;

    uint32_t w[16];
    auto ldA = [&](int row0, uint32_t* dst) {
        if (AH) ldg_tile_h<ZEROA>((const __half*)A, (__half*)Az, row0, M, tid, dst);
        else    ldg_tile<ZEROA>((const float*)A, (float*)Az, row0, M, tid, dst);
    };

    int tile = blockIdx.x;
    { uint32_t ww[16]; ldg_tile<false>(W, nullptr, 0, 128, tid, ww); sts_tile(Wf, tid, ww); }
    if (tile < ntiles) { ldA(tile * 128, w); sts_tile(Ab[0], tid, w); }
    __syncthreads();

    int buf = 0;
    for (; tile < ntiles; tile += gridDim.x) {
        const int nxt = tile + gridDim.x;
        const bool hn = nxt < ntiles;
        if (hn) ldA(nxt * 128, w);                 // overlaps MMA

        float acc[2][4][4];
#pragma unroll
        for (int t = 0; t < 2; t++)
#pragma unroll
            for (int tb = 0; tb < 4; tb++)
#pragma unroll
                for (int i = 0; i < 4; i++) acc[t][tb][i] = 0.f;
        mma_f16(Ab[buf], Wf, wm, wn, gid, tig, acc);

        if (hn) sts_tile(Ab[buf ^ 1], tid, w);
        epilogue<BIAS, RELU, ACC, RESID, OUTH>(acc, bias, R, Cout, tile * 128,
                                               wm, wn, gid, tig, M);
        __syncthreads();
        buf ^= 1;
    }
}

// ======================= fused 2-layer MLP (f16) =================================
#define FMLP_SMEM (4 * TWORDS * 4)
__global__ __launch_bounds__(512, 1)
void fmlp(const float* __restrict__ A, const float* __restrict__ Wa,
          const float* __restrict__ ba, const float* __restrict__ Wb,
          const float* __restrict__ bb, const float* __restrict__ R,
          float* __restrict__ out, int M, int ntiles)
{
    extern __shared__ uint32_t sm[];
    uint32_t* Wfa = sm;
    uint32_t* Wfb = sm + TWORDS;
    uint32_t* Ab[2] = { sm + 2 * TWORDS, sm + 3 * TWORDS };
    const int tid = threadIdx.x;
    const int lane = tid & 31, warp = tid >> 5;
    const int gid = lane >> 2, tig = lane & 3;
    const int wm = (warp >> 2) * 32, wn = (warp & 3) * 32;

    uint32_t w[16];
    int tile = blockIdx.x;
    { uint32_t ww[16]; ldg_tile<false>(Wa, nullptr, 0, 128, tid, ww); sts_tile(Wfa, tid, ww); }
    { uint32_t ww[16]; ldg_tile<false>(Wb, nullptr, 0, 128, tid, ww); sts_tile(Wfb, tid, ww); }
    if (tile < ntiles) { ldg_tile<false>(A, nullptr, tile * 128, M, tid, w); sts_tile(Ab[0], tid, w); }
    __syncthreads();

    int buf = 0;
    for (; tile < ntiles; tile += gridDim.x) {
        const int nxt = tile + gridDim.x;
        const bool hn = nxt < ntiles;
        if (hn) ldg_tile<false>(A, nullptr, nxt * 128, M, tid, w);

        float acc[2][4][4];
#pragma unroll
        for (int t = 0; t < 2; t++)
#pragma unroll
            for (int tb = 0; tb < 4; tb++)
#pragma unroll
                for (int i = 0; i < 4; i++) acc[t][tb][i] = 0.f;
        mma_f16(Ab[buf], Wfa, wm, wn, gid, tig, acc);
        __syncthreads();

        {   // hidden = relu(acc + ba) -> back into Ab[buf]
            const int gbase = wn >> 4;
#pragma unroll
            for (int t = 0; t < 2; t++) {
                const int rl = wm + t * 16 + gid;
#pragma unroll
                for (int tb = 0; tb < 4; tb++) {
                    const int cc = wn + tb * 8 + tig * 2;
                    const int g = gbase + (tb >> 1);
                    const int p = 2 * tig + (tb & 1);
                    float2 b2 = *(const float2*)(ba + cc);
                    Ab[buf][widx(rl,     g, p)] = pk(fmaxf(acc[t][tb][0] + b2.x, 0.f),
                                                     fmaxf(acc[t][tb][1] + b2.y, 0.f));
                    Ab[buf][widx(rl + 8, g, p)] = pk(fmaxf(acc[t][tb][2] + b2.x, 0.f),
                                                     fmaxf(acc[t][tb][3] + b2.y, 0.f));
                }
            }
        }
        __syncthreads();

#pragma unroll
        for (int t = 0; t < 2; t++)
#pragma unroll
            for (int tb = 0; tb < 4; tb++)
#pragma unroll
                for (int i = 0; i < 4; i++) acc[t][tb][i] = 0.f;
        mma_f16(Ab[buf], Wfb, wm, wn, gid, tig, acc);

        if (hn) sts_tile(Ab[buf ^ 1], tid, w);
        epilogue<true, false, false, true, false>(acc, bb, R, out, tile * 128,
                                                  wm, wn, gid, tig, M);
        __syncthreads();
        buf ^= 1;
    }
}

// ------------- elementwise: dst[r] = relu(y[s[r]] + y[e[r]] + bias) --------------
__global__ void edge_kernel(const __half* __restrict__ y, const int* __restrict__ s,
                            const int* __restrict__ e, const float* __restrict__ b,
                            float* __restrict__ dst, int M)
{
    const int w = (blockIdx.x * blockDim.x + threadIdx.x) >> 5;
    const int lane = threadIdx.x & 31;
    if (w >= M) return;
    float4 va = ldy(y, s[w], lane);
    float4 vb = ldy(y, e[w], lane);
    float4 bb = *(const float4*)(b + lane * 4);
    float4 o;
    o.x = fmaxf(va.x + vb.x + bb.x, 0.f);
    o.y = fmaxf(va.y + vb.y + bb.y, 0.f);
    o.z = fmaxf(va.z + vb.z + bb.z, 0.f);
    o.w = fmaxf(va.w + vb.w + bb.w, 0.f);
    *(float4*)(dst + (size_t)w * C + lane * 4) = o;
}

// ------------- scatter: a0[s[r]] += relu(y[r] + bias)  (fp32 dst, tiny) ----------
__global__ void scat_node_kernel(const __half* __restrict__ y, const int* __restrict__ s,
                                 const float* __restrict__ b, float* __restrict__ a0, int M)
{
    const int w = (blockIdx.x * blockDim.x + threadIdx.x) >> 5;
    const int lane = threadIdx.x & 31;
    if (w >= M) return;
    const int d = s[w];
    float4 v = ldy(y, w, lane);
    float4 bb = *(const float4*)(b + lane * 4);
    red4(a0 + (size_t)d * C + lane * 4,
         fmaxf(v.x + bb.x, 0.f), fmaxf(v.y + bb.y, 0.f),
         fmaxf(v.z + bb.z, 0.f), fmaxf(v.w + bb.w, 0.f));
}

// ------- tri scatter (f16 dst): dst[id] += relu(ya[i1] + yb[i2] + bias) ----------
__global__ void tri_scat_kernel(const __half* __restrict__ ya, const __half* __restrict__ yb,
                                const int* __restrict__ id, const int* __restrict__ i1,
                                const int* __restrict__ i2, const float* __restrict__ b,
                                __half* __restrict__ dst, int M)
{
    const int w = (blockIdx.x * blockDim.x + threadIdx.x) >> 5;
    const int lane = threadIdx.x & 31;
    if (w >= M) return;
    const int d = id[w];
    float4 va = ldy(ya, i1[w], lane);
    float4 vb = ldy(yb, i2[w], lane);
    float4 bb = *(const float4*)(b + lane * 4);
    red2h(dst + (size_t)d * C + lane * 4,
          fmaxf(va.x + vb.x + bb.x, 0.f), fmaxf(va.y + vb.y + bb.y, 0.f),
          fmaxf(va.z + vb.z + bb.z, 0.f), fmaxf(va.w + vb.w + bb.w, 0.f));
}

// ------- merged t112 (f16 dsts) --------------------------------------------------
__global__ void tri112_kernel(const __half* __restrict__ y1, const __half* __restrict__ y2,
                              const int* __restrict__ t0a, const int* __restrict__ t1a,
                              const int* __restrict__ t2a, const float* __restrict__ b,
                              __half* __restrict__ tmpA, __half* __restrict__ tmpB, int M)
{
    const int w = (blockIdx.x * blockDim.x + threadIdx.x) >> 5;
    const int lane = threadIdx.x & 31;
    if (w >= M) return;
    const int t0 = t0a[w], t1 = t1a[w], t2 = t2a[w];
    float4 f0 = ldy(y1, t0, lane);
    float4 f1 = ldy(y1, t1, lane);
    float4 f2 = ldy(y2, t2, lane);
    float4 bb = *(const float4*)(b + lane * 4);
    red2h(tmpA + (size_t)t2 * C + lane * 4,
          fmaxf(f0.x + f1.x + bb.x, 0.f), fmaxf(f0.y + f1.y + bb.y, 0.f),
          fmaxf(f0.z + f1.z + bb.z, 0.f), fmaxf(f0.w + f1.w + bb.w, 0.f));
    red2h(tmpB + (size_t)t0 * C + lane * 4,
          fmaxf(f1.x + f2.x + bb.x, 0.f), fmaxf(f1.y + f2.y + bb.y, 0.f),
          fmaxf(f1.z + f2.z + bb.z, 0.f), fmaxf(f1.w + f2.w + bb.w, 0.f));
}

// ------- a1[r] += v[r] + v[inv1[r]] + bias + x1[r]  (v is f16) -------------------
__global__ void fuse_a1_kernel(float* __restrict__ a1, const __half* __restrict__ v,
                               const int* __restrict__ inv1, const float* __restrict__ b,
                               const float* __restrict__ x1, int M)
{
    const int w = (blockIdx.x * blockDim.x + threadIdx.x) >> 5;
    const int lane = threadIdx.x & 31;
    if (w >= M) return;
    const int g = inv1[w];
    float4 va = *(const float4*)(a1 + (size_t)w * C + lane * 4);
    float4 vv = ldy(v, w, lane);
    float4 vg = ldy(v, g, lane);
    float4 bb = *(const float4*)(b + lane * 4);
    float4 vx = *(const float4*)(x1 + (size_t)w * C + lane * 4);
    float4 o;
    o.x = va.x + vv.x + vg.x + bb.x + vx.x;
    o.y = va.y + vv.y + vg.y + bb.y + vx.y;
    o.z = va.z + vv.z + vg.z + bb.z + vx.z;
    o.w = va.w + vv.w + vg.w + bb.w + vx.w;
    *(float4*)(a1 + (size_t)w * C + lane * 4) = o;
}

// ================================================================================
template<bool BIAS, bool RELU, bool ACC, bool RESID, bool ZEROA, bool OUTH, bool AH>
static inline void run_tgemm(const void* A, const float* W, const float* b,
                             const float* R, void* Co, void* Az, int M)
{
    int nt = (M + 127) / 128;
    int grid = nt < 148 ? nt : 148;
    cudaFuncSetAttribute(tgemm<BIAS, RELU, ACC, RESID, ZEROA, OUTH, AH>,
                         cudaFuncAttributeMaxDynamicSharedMemorySize, GEMM_SMEM);
    tgemm<BIAS, RELU, ACC, RESID, ZEROA, OUTH, AH><<<grid, 512, GEMM_SMEM>>>(
        A, W, b, R, Co, Az, M, nt);
}

static inline void run_fmlp(const float* A, const float* Wa, const float* ba,
                            const float* Wb, const float* bb, const float* R,
                            float* out, int M)
{
    int nt = (M + 127) / 128;
    int grid = nt < 148 ? nt : 148;
    cudaFuncSetAttribute(fmlp, cudaFuncAttributeMaxDynamicSharedMemorySize, FMLP_SMEM);
    fmlp<<<grid, 512, FMLP_SMEM>>>(A, Wa, ba, Wb, bb, R, out, M, nt);
}

extern "C" void kernel_launch(void* const* d_in, const int* in_sizes, int n_in,
                              void* d_out, int out_size)
{
    (void)in_sizes; (void)n_in; (void)out_size;
    const float* x0   = (const float*)d_in[0];
    const float* x1   = (const float*)d_in[1];
    const float* x2   = (const float*)d_in[2];
    const int*   ei1  = (const int*)d_in[3];
    const int*   ei2  = (const int*)d_in[4];
    const int*   t111 = (const int*)d_in[5];
    const int*   t222 = (const int*)d_in[6];
    const int*   t112 = (const int*)d_in[7];
    const int*   inv1 = (const int*)d_in[8];
    const float* WiW  = (const float*)d_in[10]; const float* Wib  = (const float*)d_in[11];
    const float* l111W= (const float*)d_in[12]; const float* l111b= (const float*)d_in[13];
    const float* l222W= (const float*)d_in[14]; const float* l222b= (const float*)d_in[15];
    const float* l211W= (const float*)d_in[16]; const float* l211b= (const float*)d_in[17];
    const float* m0aW = (const float*)d_in[18]; const float* m0ab = (const float*)d_in[19];
    const float* m0bW = (const float*)d_in[20]; const float* m0bb = (const float*)d_in[21];
    const float* m1aW = (const float*)d_in[22]; const float* m1ab = (const float*)d_in[23];
    const float* m1bW = (const float*)d_in[24]; const float* m1bb = (const float*)d_in[25];
    const float* m2aW = (const float*)d_in[26]; const float* m2ab = (const float*)d_in[27];
    const float* m2bW = (const float*)d_in[28]; const float* m2bb = (const float*)d_in[29];
    float* out = (float*)d_out;

    __half *y0, *y1, *y2, *tmp, *tmp2, *tmp3;
    float *a0, *a1, *a2;
    cudaGetSymbolAddress((void**)&y0,   g_y0h);
    cudaGetSymbolAddress((void**)&y1,   g_y1h);
    cudaGetSymbolAddress((void**)&y2,   g_y2h);
    cudaGetSymbolAddress((void**)&a0,   g_a0);
    cudaGetSymbolAddress((void**)&a1,   g_a1);
    cudaGetSymbolAddress((void**)&a2,   g_a2);
    cudaGetSymbolAddress((void**)&tmp,  g_tmp);
    cudaGetSymbolAddress((void**)&tmp2, g_tmp2);
    cudaGetSymbolAddress((void**)&tmp3, g_tmp3);

    const dim3 blk(256);
    auto eg = [](int M) { return dim3((unsigned)((M + 7) / 8)); };

    // a0 starts as x0 (residual fold). tmp/tmp3 are zero: device globals start
    // zeroed and every consumer GEMM below re-zeroes via ZEROA before replay.
    cudaMemcpyAsync(a0, x0, (size_t)N0 * C * sizeof(float), cudaMemcpyDeviceToDevice, 0);

    // projections (f16 outputs)                                        launches 1-3
    run_tgemm<false,false,false,false,false,true,false>(x0, WiW, nullptr, nullptr, y0, nullptr, N0);
    run_tgemm<false,false,false,false,false,true,false>(x1, WiW, nullptr, nullptr, y1, nullptr, E1V);
    run_tgemm<false,false,false,false,false,true,false>(x2, WiW, nullptr, nullptr, y2, nullptr, E2V);

    edge_kernel<<<eg(E1V), blk>>>(y0, ei1, ei1 + E1V, Wib, a1, E1V);      // 4
    edge_kernel<<<eg(E2V), blk>>>(y0, ei2, ei2 + E2V, Wib, a2, E2V);      // 5
    // launch 6 = ncu -s5 -c1 profiled slot: the f16-red tri scatter
    tri_scat_kernel<<<eg(TV), blk>>>(y1, y1, t111, t111 + TV, t111 + 2 * TV, Wib, tmp, TV);

    scat_node_kernel<<<eg(E1V), blk>>>(y1, ei1, Wib, a0, E1V);
    scat_node_kernel<<<eg(E2V), blk>>>(y2, ei2, Wib, a0, E2V);

    // aggr (1,1,1): tmp -> a1 (AH read; ZEROA re-zeroes tmp)
    run_tgemm<true,false,true,false,true,false,true>(tmp, l111W, l111b, nullptr, a1, tmp, E1V);

    // aggr (2,2,2)
    tri_scat_kernel<<<eg(TV), blk>>>(y2, y2, t222, t222 + TV, t222 + 2 * TV, Wib, tmp, TV);
    run_tgemm<true,false,true,false,true,false,true>(tmp, l222W, l222b, nullptr, a2, tmp, E2V);

    // merged aggr (1,1,2): one gather pass fills both f16 segment buffers
    tri112_kernel<<<eg(TV), blk>>>(y1, y2, t112, t112 + TV, t112 + 2 * TV, Wib,
                                   tmp, tmp3, TV);
    // part a: tmp -> a2 (+x2 residual); ZEROA restores tmp
    run_tgemm<true,false,true,true,true,false,true>(tmp, l211W, l211b, x2, a2, tmp, E2V);
    // part b: v = tmp3 @ l211W^T -> tmp2 (f16); ZEROA restores tmp3
    run_tgemm<false,false,false,false,true,true,true>(tmp3, l211W, nullptr, nullptr, tmp2, tmp3, E1V);
    fuse_a1_kernel<<<eg(E1V), blk>>>(a1, tmp2, inv1, l211b, x1, E1V);

    // fused output MLPs (a-buffers hold x + a) + residual
    run_fmlp(a0, m0aW, m0ab, m0bW, m0bb, x0, out, N0);
    run_fmlp(a1, m1aW, m1ab, m1bW, m1bb, x1, out + (size_t)N0 * C, E1V);
    run_fmlp(a2, m2aW, m2ab, m2bW, m2bb, x2, out + ((size_t)N0 + E1V) * C, E2V);
}

// round 10
// speedup vs baseline: 1.4264x; 1.4264x over previous
#include <cuda_runtime.h>
#include <cuda_fp16.h>
#include <cstdint>
#include <cstddef>

#define C   128
#define N0  20000
#define E1V 500000
#define E2V 500000
#define TV  500000

// ---------------- static device scratch (no allocations allowed) ----------------
__device__ __half g_y0h[(size_t)N0 * C];
__device__ __half g_y1h[(size_t)E1V * C];
__device__ __half g_y2h[(size_t)E2V * C];
__device__ float  g_a0[(size_t)N0 * C];
__device__ float  g_a1[(size_t)E1V * C];
__device__ float  g_a2[(size_t)E2V * C];
__device__ __half g_v[(size_t)E1V * C];     // part-b linear output (f16, RED target)

__device__ __forceinline__ void red4(float* p, float a, float b, float c, float d) {
    asm volatile("red.global.add.v4.f32 [%0], {%1,%2,%3,%4};"
                 :: "l"(p), "f"(a), "f"(b), "f"(c), "f"(d) : "memory");
}
__device__ __forceinline__ void red2(float* p, float a, float b) {
    asm volatile("red.global.add.v2.f32 [%0], {%1,%2};"
                 :: "l"(p), "f"(a), "f"(b) : "memory");
}
__device__ __forceinline__ void redh1(__half* p, uint32_t v) {
    asm volatile("red.global.add.noftz.f16x2 [%0], %1;"
                 :: "l"(p), "r"(v) : "memory");
}
// pack two f32 -> f16x2
__device__ __forceinline__ uint32_t pk(float lo, float hi) {
    uint32_t d;
    asm("cvt.rn.f16x2.f32 %0, %1, %2;" : "=r"(d) : "f"(hi), "f"(lo));
    return d;
}
// read 4 consecutive f16 of row as floats
__device__ __forceinline__ float4 ldy(const __half* y, int row, int lane) {
    uint2 u = *(const uint2*)(y + (size_t)row * C + lane * 4);
    __half2 h0 = *(__half2*)&u.x, h1 = *(__half2*)&u.y;
    float2 a = __half22float2(h0), b = __half22float2(h1);
    return make_float4(a.x, a.y, b.x, b.y);
}
// relu(ha + hb + bias) packed
__device__ __forceinline__ uint32_t gath_word(uint32_t ua, uint32_t ub, float2 bi) {
    float2 fa = __half22float2(*(__half2*)&ua);
    float2 fb = __half22float2(*(__half2*)&ub);
    return pk(fmaxf(fa.x + fb.x + bi.x, 0.f), fmaxf(fa.y + fb.y + bi.y, 0.f));
}

// ---- f16 tile layout: 128 rows, 8 k16-groups of 8 f16x2 words, row stride 72 ----
#define ROWW 72
#define TWORDS (128 * ROWW)
__device__ __forceinline__ int widx(int r, int g, int p) { return r * ROWW + g * 8 + p; }

// permute linear words [0..7] -> [0,4,1,5,2,6,3,7] per 8-word half
__device__ __forceinline__ void permute16(const uint32_t* lin, uint32_t* w) {
#pragma unroll
    for (int h = 0; h < 2; h++) {
        const uint32_t* i8 = lin + h * 8;
        uint32_t* o = w + h * 8;
        o[0] = i8[0]; o[1] = i8[4]; o[2] = i8[1]; o[3] = i8[5];
        o[4] = i8[2]; o[5] = i8[6]; o[6] = i8[3]; o[7] = i8[7];
    }
}

// LDG a 128x128 fp32 tile -> 16 packed f16x2 regs (for W and fp32 A).
__device__ __forceinline__ void ldg_tile(const float* A, int row0, int M,
                                         int tid, uint32_t* w)
{
    const int row = row0 + (tid >> 2), q = tid & 3;
    uint32_t lin[16];
#pragma unroll
    for (int j = 0; j < 16; j++) lin[j] = 0;
    if (row < M) {
        const float4* g = (const float4*)(A + (size_t)row * C + q * 32);
#pragma unroll
        for (int j = 0; j < 8; j++) {
            float4 f = g[j];
            lin[j * 2 + 0] = pk(f.x, f.y);
            lin[j * 2 + 1] = pk(f.z, f.w);
        }
    }
    permute16(lin, w);
}

// Gathered A tile: row r = relu(ya[iA[r]] + yb[iB[r]] + binner), f16 sources.
__device__ __forceinline__ void ldg_gather(const __half* ya, const __half* yb,
                                           const int* iA, const int* iB,
                                           const float* binner, int row0, int M,
                                           int tid, uint32_t* w)
{
    const int r = row0 + (tid >> 2), q = tid & 3;
    uint32_t lin[16];
    if (r < M) {
        const int a = iA[r], b = iB[r];
        const uint4* ga = (const uint4*)(ya + (size_t)a * C + q * 32);
        const uint4* gb = (const uint4*)(yb + (size_t)b * C + q * 32);
        uint4 va[4], vb[4];
#pragma unroll
        for (int j = 0; j < 4; j++) { va[j] = ga[j]; vb[j] = gb[j]; }
        const float* bi = binner + q * 32;
#pragma unroll
        for (int j = 0; j < 4; j++) {
            float2 b0 = *(const float2*)(bi + j * 8 + 0);
            float2 b1 = *(const float2*)(bi + j * 8 + 2);
            float2 b2 = *(const float2*)(bi + j * 8 + 4);
            float2 b3 = *(const float2*)(bi + j * 8 + 6);
            lin[j * 4 + 0] = gath_word(va[j].x, vb[j].x, b0);
            lin[j * 4 + 1] = gath_word(va[j].y, vb[j].y, b1);
            lin[j * 4 + 2] = gath_word(va[j].z, vb[j].z, b2);
            lin[j * 4 + 3] = gath_word(va[j].w, vb[j].w, b3);
        }
    } else {
#pragma unroll
        for (int j = 0; j < 16; j++) lin[j] = 0;
    }
    permute16(lin, w);
}

__device__ __forceinline__ void sts_tile(uint32_t* buf, int tid, const uint32_t* w)
{
    const int row = tid >> 2, q = tid & 3;
    *(uint4*)(buf + widx(row, 2 * q,     0)) = make_uint4(w[0],  w[1],  w[2],  w[3]);
    *(uint4*)(buf + widx(row, 2 * q,     4)) = make_uint4(w[4],  w[5],  w[6],  w[7]);
    *(uint4*)(buf + widx(row, 2 * q + 1, 0)) = make_uint4(w[8],  w[9],  w[10], w[11]);
    *(uint4*)(buf + widx(row, 2 * q + 1, 4)) = make_uint4(w[12], w[13], w[14], w[15]);
}

__device__ __forceinline__ void mma_f16(const uint32_t* Ab, const uint32_t* Wb,
                                        int wm, int wn, int gid, int tig,
                                        float acc[2][4][4])
{
#pragma unroll
    for (int g = 0; g < 8; g++) {
        uint32_t af[2][4], bf[4][2];
#pragma unroll
        for (int t = 0; t < 2; t++) {
            const int rl = wm + t * 16 + gid;
            uint2 lo = *(const uint2*)(Ab + widx(rl,     g, tig * 2));
            uint2 hi = *(const uint2*)(Ab + widx(rl + 8, g, tig * 2));
            af[t][0] = lo.x; af[t][1] = hi.x; af[t][2] = lo.y; af[t][3] = hi.y;
        }
#pragma unroll
        for (int tb = 0; tb < 4; tb++) {
            const int n = wn + tb * 8 + gid;
            uint2 b = *(const uint2*)(Wb + widx(n, g, tig * 2));
            bf[tb][0] = b.x; bf[tb][1] = b.y;
        }
#pragma unroll
        for (int t = 0; t < 2; t++)
#pragma unroll
            for (int tb = 0; tb < 4; tb++)
                asm("mma.sync.aligned.m16n8k16.row.col.f32.f16.f16.f32 "
                    "{%0,%1,%2,%3}, {%4,%5,%6,%7}, {%8,%9}, {%0,%1,%2,%3};"
                    : "+f"(acc[t][tb][0]), "+f"(acc[t][tb][1]),
                      "+f"(acc[t][tb][2]), "+f"(acc[t][tb][3])
                    : "r"(af[t][0]), "r"(af[t][1]), "r"(af[t][2]), "r"(af[t][3]),
                      "r"(bf[tb][0]), "r"(bf[tb][1]));
    }
}

#define GEMM_SMEM (3 * TWORDS * 4)

// ===================== projection GEMM: y(half) = A(f32) @ W^T ===================
__global__ __launch_bounds__(512, 1)
void tgemm(const float* __restrict__ A, const float* __restrict__ W,
           __half* __restrict__ Cout, int M, int ntiles)
{
    extern __shared__ uint32_t sm[];
    uint32_t* Wf = sm;
    uint32_t* Ab[2] = { sm + TWORDS, sm + 2 * TWORDS };
    const int tid = threadIdx.x;
    const int lane = tid & 31, warp = tid >> 5;
    const int gid = lane >> 2, tig = lane & 3;
    const int wm = (warp >> 2) * 32, wn = (warp & 3) * 32;

    uint32_t w[16];
    int tile = blockIdx.x;
    { uint32_t ww[16]; ldg_tile(W, 0, 128, tid, ww); sts_tile(Wf, tid, ww); }
    if (tile < ntiles) { ldg_tile(A, tile * 128, M, tid, w); sts_tile(Ab[0], tid, w); }
    __syncthreads();

    int buf = 0;
    for (; tile < ntiles; tile += gridDim.x) {
        const int nxt = tile + gridDim.x;
        const bool hn = nxt < ntiles;
        if (hn) ldg_tile(A, nxt * 128, M, tid, w);

        float acc[2][4][4];
#pragma unroll
        for (int t = 0; t < 2; t++)
#pragma unroll
            for (int tb = 0; tb < 4; tb++)
#pragma unroll
                for (int i = 0; i < 4; i++) acc[t][tb][i] = 0.f;
        mma_f16(Ab[buf], Wf, wm, wn, gid, tig, acc);

        if (hn) sts_tile(Ab[buf ^ 1], tid, w);
#pragma unroll
        for (int t = 0; t < 2; t++) {
            const int r = tile * 128 + wm + t * 16 + gid;
#pragma unroll
            for (int tb = 0; tb < 4; tb++) {
                const int cc = wn + tb * 8 + tig * 2;
                if (r < M)
                    *(uint32_t*)(Cout + (size_t)r * C + cc) =
                        pk(acc[t][tb][0], acc[t][tb][1]);
                if (r + 8 < M)
                    *(uint32_t*)(Cout + (size_t)(r + 8) * C + cc) =
                        pk(acc[t][tb][2], acc[t][tb][3]);
            }
        }
        __syncthreads();
        buf ^= 1;
    }
}

// ============ gather-GEMM-scatter: dst[iD[r]] += relu(ya[iA]+yb[iB]+bi) @ W^T ====
template<bool OUTH>
__global__ __launch_bounds__(512, 1)
void ggemm(const __half* __restrict__ ya, const __half* __restrict__ yb,
           const int* __restrict__ iA, const int* __restrict__ iB,
           const int* __restrict__ iD, const float* __restrict__ binner,
           const float* __restrict__ W, void* __restrict__ dst, int M, int ntiles)
{
    extern __shared__ uint32_t sm[];
    uint32_t* Wf = sm;
    uint32_t* Ab[2] = { sm + TWORDS, sm + 2 * TWORDS };
    const int tid = threadIdx.x;
    const int lane = tid & 31, warp = tid >> 5;
    const int gid = lane >> 2, tig = lane & 3;
    const int wm = (warp >> 2) * 32, wn = (warp & 3) * 32;

    uint32_t w[16];
    int tile = blockIdx.x;
    { uint32_t ww[16]; ldg_tile(W, 0, 128, tid, ww); sts_tile(Wf, tid, ww); }
    if (tile < ntiles) {
        ldg_gather(ya, yb, iA, iB, binner, tile * 128, M, tid, w);
        sts_tile(Ab[0], tid, w);
    }
    __syncthreads();

    int buf = 0;
    for (; tile < ntiles; tile += gridDim.x) {
        const int nxt = tile + gridDim.x;
        const bool hn = nxt < ntiles;
        if (hn) ldg_gather(ya, yb, iA, iB, binner, nxt * 128, M, tid, w);

        float acc[2][4][4];
#pragma unroll
        for (int t = 0; t < 2; t++)
#pragma unroll
            for (int tb = 0; tb < 4; tb++)
#pragma unroll
                for (int i = 0; i < 4; i++) acc[t][tb][i] = 0.f;
        mma_f16(Ab[buf], Wf, wm, wn, gid, tig, acc);

        if (hn) sts_tile(Ab[buf ^ 1], tid, w);

        // scatter epilogue: RED output rows into dst[iD[r]]
#pragma unroll
        for (int t = 0; t < 2; t++) {
            const int r = tile * 128 + wm + t * 16 + gid;
            if (r < M) {
                const size_t base = (size_t)iD[r] * C;
#pragma unroll
                for (int tb = 0; tb < 4; tb++) {
                    const int cc = wn + tb * 8 + tig * 2;
                    if (OUTH)
                        redh1((__half*)dst + base + cc, pk(acc[t][tb][0], acc[t][tb][1]));
                    else
                        red2((float*)dst + base + cc, acc[t][tb][0], acc[t][tb][1]);
                }
            }
            if (r + 8 < M) {
                const size_t base = (size_t)iD[r + 8] * C;
#pragma unroll
                for (int tb = 0; tb < 4; tb++) {
                    const int cc = wn + tb * 8 + tig * 2;
                    if (OUTH)
                        redh1((__half*)dst + base + cc, pk(acc[t][tb][2], acc[t][tb][3]));
                    else
                        red2((float*)dst + base + cc, acc[t][tb][2], acc[t][tb][3]);
                }
            }
        }
        __syncthreads();
        buf ^= 1;
    }
}

// ======================= fused 2-layer MLP (f16) =================================
#define FMLP_SMEM (4 * TWORDS * 4)
__global__ __launch_bounds__(512, 1)
void fmlp(const float* __restrict__ A, const float* __restrict__ Wa,
          const float* __restrict__ ba, const float* __restrict__ Wb,
          const float* __restrict__ bb, const float* __restrict__ R,
          float* __restrict__ out, __half* __restrict__ zp, int M, int ntiles)
{
    extern __shared__ uint32_t sm[];
    uint32_t* Wfa = sm;
    uint32_t* Wfb = sm + TWORDS;
    uint32_t* Ab[2] = { sm + 2 * TWORDS, sm + 3 * TWORDS };
    const int tid = threadIdx.x;
    const int lane = tid & 31, warp = tid >> 5;
    const int gid = lane >> 2, tig = lane & 3;
    const int wm = (warp >> 2) * 32, wn = (warp & 3) * 32;
    const int lrow = tid >> 2, q = tid & 3;

    auto ld = [&](int row0, uint32_t* dst) {
        ldg_tile(A, row0, M, tid, dst);
        const int r = row0 + lrow;
        if (zp && r < M) {
            uint4* z = (uint4*)(zp + (size_t)r * C + q * 32);
#pragma unroll
            for (int j = 0; j < 4; j++) z[j] = make_uint4(0, 0, 0, 0);
        }
    };

    uint32_t w[16];
    int tile = blockIdx.x;
    { uint32_t ww[16]; ldg_tile(Wa, 0, 128, tid, ww); sts_tile(Wfa, tid, ww); }
    { uint32_t ww[16]; ldg_tile(Wb, 0, 128, tid, ww); sts_tile(Wfb, tid, ww); }
    if (tile < ntiles) { ld(tile * 128, w); sts_tile(Ab[0], tid, w); }
    __syncthreads();

    int buf = 0;
    for (; tile < ntiles; tile += gridDim.x) {
        const int nxt = tile + gridDim.x;
        const bool hn = nxt < ntiles;
        if (hn) ld(nxt * 128, w);

        float acc[2][4][4];
#pragma unroll
        for (int t = 0; t < 2; t++)
#pragma unroll
            for (int tb = 0; tb < 4; tb++)
#pragma unroll
                for (int i = 0; i < 4; i++) acc[t][tb][i] = 0.f;
        mma_f16(Ab[buf], Wfa, wm, wn, gid, tig, acc);
        __syncthreads();

        {   // hidden = relu(acc + ba) -> back into Ab[buf]
            const int gbase = wn >> 4;
#pragma unroll
            for (int t = 0; t < 2; t++) {
                const int rl = wm + t * 16 + gid;
#pragma unroll
                for (int tb = 0; tb < 4; tb++) {
                    const int cc = wn + tb * 8 + tig * 2;
                    const int g = gbase + (tb >> 1);
                    const int p = 2 * tig + (tb & 1);
                    float2 b2 = *(const float2*)(ba + cc);
                    Ab[buf][widx(rl,     g, p)] = pk(fmaxf(acc[t][tb][0] + b2.x, 0.f),
                                                     fmaxf(acc[t][tb][1] + b2.y, 0.f));
                    Ab[buf][widx(rl + 8, g, p)] = pk(fmaxf(acc[t][tb][2] + b2.x, 0.f),
                                                     fmaxf(acc[t][tb][3] + b2.y, 0.f));
                }
            }
        }
        __syncthreads();

#pragma unroll
        for (int t = 0; t < 2; t++)
#pragma unroll
            for (int tb = 0; tb < 4; tb++)
#pragma unroll
                for (int i = 0; i < 4; i++) acc[t][tb][i] = 0.f;
        mma_f16(Ab[buf], Wfb, wm, wn, gid, tig, acc);

        if (hn) sts_tile(Ab[buf ^ 1], tid, w);
#pragma unroll
        for (int t = 0; t < 2; t++) {
            const int r = tile * 128 + wm + t * 16 + gid;
#pragma unroll
            for (int tb = 0; tb < 4; tb++) {
                const int cc = wn + tb * 8 + tig * 2;
                float2 bb2 = *(const float2*)(bb + cc);
                if (r < M) {
                    float2 o = *(const float2*)(R + (size_t)r * C + cc);
                    *(float2*)(out + (size_t)r * C + cc) =
                        make_float2(acc[t][tb][0] + bb2.x + o.x,
                                    acc[t][tb][1] + bb2.y + o.y);
                }
                if (r + 8 < M) {
                    float2 o = *(const float2*)(R + (size_t)(r + 8) * C + cc);
                    *(float2*)(out + (size_t)(r + 8) * C + cc) =
                        make_float2(acc[t][tb][2] + bb2.x + o.x,
                                    acc[t][tb][3] + bb2.y + o.y);
                }
            }
        }
        __syncthreads();
        buf ^= 1;
    }
}

// ---- edge: dst[r] = relu(y[s]+y[e]+bi) + x[r] + b1 + b2 -------------------------
__global__ void edge_kernel(const __half* __restrict__ y, const int* __restrict__ s,
                            const int* __restrict__ e, const float* __restrict__ bi,
                            const float* __restrict__ x, const float* __restrict__ b1,
                            const float* __restrict__ b2, float* __restrict__ dst, int M)
{
    const int w = (blockIdx.x * blockDim.x + threadIdx.x) >> 5;
    const int lane = threadIdx.x & 31;
    if (w >= M) return;
    float4 va = ldy(y, s[w], lane);
    float4 vb = ldy(y, e[w], lane);
    float4 bb = *(const float4*)(bi + lane * 4);
    float4 c1 = *(const float4*)(b1 + lane * 4);
    float4 c2 = *(const float4*)(b2 + lane * 4);
    float4 xx = *(const float4*)(x + (size_t)w * C + lane * 4);
    float4 o;
    o.x = fmaxf(va.x + vb.x + bb.x, 0.f) + xx.x + c1.x + c2.x;
    o.y = fmaxf(va.y + vb.y + bb.y, 0.f) + xx.y + c1.y + c2.y;
    o.z = fmaxf(va.z + vb.z + bb.z, 0.f) + xx.z + c1.z + c2.z;
    o.w = fmaxf(va.w + vb.w + bb.w, 0.f) + xx.w + c1.w + c2.w;
    *(float4*)(dst + (size_t)w * C + lane * 4) = o;
}

// ---- scatter: a0[s[r]] += relu(y[r] + bias) -------------------------------------
__global__ void scat_node_kernel(const __half* __restrict__ y, const int* __restrict__ s,
                                 const float* __restrict__ b, float* __restrict__ a0, int M)
{
    const int w = (blockIdx.x * blockDim.x + threadIdx.x) >> 5;
    const int lane = threadIdx.x & 31;
    if (w >= M) return;
    const int d = s[w];
    float4 v = ldy(y, w, lane);
    float4 bb = *(const float4*)(b + lane * 4);
    red4(a0 + (size_t)d * C + lane * 4,
         fmaxf(v.x + bb.x, 0.f), fmaxf(v.y + bb.y, 0.f),
         fmaxf(v.z + bb.z, 0.f), fmaxf(v.w + bb.w, 0.f));
}

// ---- a1[r] += v[r] + v[inv1[r]]  (v f16) ----------------------------------------
__global__ void fuse_a1_kernel(float* __restrict__ a1, const __half* __restrict__ v,
                               const int* __restrict__ inv1, int M)
{
    const int w = (blockIdx.x * blockDim.x + threadIdx.x) >> 5;
    const int lane = threadIdx.x & 31;
    if (w >= M) return;
    const int g = inv1[w];
    float4 va = *(const float4*)(a1 + (size_t)w * C + lane * 4);
    float4 vv = ldy(v, w, lane);
    float4 vg = ldy(v, g, lane);
    float4 o;
    o.x = va.x + vv.x + vg.x;
    o.y = va.y + vv.y + vg.y;
    o.z = va.z + vv.z + vg.z;
    o.w = va.w + vv.w + vg.w;
    *(float4*)(a1 + (size_t)w * C + lane * 4) = o;
}

// ================================================================================
static inline void run_tgemm(const float* A, const float* W, __half* Co, int M)
{
    int nt = (M + 127) / 128;
    int grid = nt < 148 ? nt : 148;
    cudaFuncSetAttribute(tgemm, cudaFuncAttributeMaxDynamicSharedMemorySize, GEMM_SMEM);
    tgemm<<<grid, 512, GEMM_SMEM>>>(A, W, Co, M, nt);
}

template<bool OUTH>
static inline void run_ggemm(const __half* ya, const __half* yb, const int* iA,
                             const int* iB, const int* iD, const float* bi,
                             const float* W, void* dst, int M)
{
    int nt = (M + 127) / 128;
    int grid = nt < 148 ? nt : 148;
    cudaFuncSetAttribute(ggemm<OUTH>, cudaFuncAttributeMaxDynamicSharedMemorySize, GEMM_SMEM);
    ggemm<OUTH><<<grid, 512, GEMM_SMEM>>>(ya, yb, iA, iB, iD, bi, W, dst, M, nt);
}

static inline void run_fmlp(const float* A, const float* Wa, const float* ba,
                            const float* Wb, const float* bb, const float* R,
                            float* out, __half* zp, int M)
{
    int nt = (M + 127) / 128;
    int grid = nt < 148 ? nt : 148;
    cudaFuncSetAttribute(fmlp, cudaFuncAttributeMaxDynamicSharedMemorySize, FMLP_SMEM);
    fmlp<<<grid, 512, FMLP_SMEM>>>(A, Wa, ba, Wb, bb, R, out, zp, M, nt);
}

extern "C" void kernel_launch(void* const* d_in, const int* in_sizes, int n_in,
                              void* d_out, int out_size)
{
    (void)in_sizes; (void)n_in; (void)out_size;
    const float* x0   = (const float*)d_in[0];
    const float* x1   = (const float*)d_in[1];
    const float* x2   = (const float*)d_in[2];
    const int*   ei1  = (const int*)d_in[3];
    const int*   ei2  = (const int*)d_in[4];
    const int*   t111 = (const int*)d_in[5];
    const int*   t222 = (const int*)d_in[6];
    const int*   t112 = (const int*)d_in[7];
    const int*   inv1 = (const int*)d_in[8];
    const float* WiW  = (const float*)d_in[10]; const float* Wib  = (const float*)d_in[11];
    const float* l111W= (const float*)d_in[12]; const float* l111b= (const float*)d_in[13];
    const float* l222W= (const float*)d_in[14]; const float* l222b= (const float*)d_in[15];
    const float* l211W= (const float*)d_in[16]; const float* l211b= (const float*)d_in[17];
    const float* m0aW = (const float*)d_in[18]; const float* m0ab = (const float*)d_in[19];
    const float* m0bW = (const float*)d_in[20]; const float* m0bb = (const float*)d_in[21];
    const float* m1aW = (const float*)d_in[22]; const float* m1ab = (const float*)d_in[23];
    const float* m1bW = (const float*)d_in[24]; const float* m1bb = (const float*)d_in[25];
    const float* m2aW = (const float*)d_in[26]; const float* m2ab = (const float*)d_in[27];
    const float* m2bW = (const float*)d_in[28]; const float* m2bb = (const float*)d_in[29];
    float* out = (float*)d_out;

    __half *y0, *y1, *y2, *v;
    float *a0, *a1, *a2;
    cudaGetSymbolAddress((void**)&y0, g_y0h);
    cudaGetSymbolAddress((void**)&y1, g_y1h);
    cudaGetSymbolAddress((void**)&y2, g_y2h);
    cudaGetSymbolAddress((void**)&a0, g_a0);
    cudaGetSymbolAddress((void**)&a1, g_a1);
    cudaGetSymbolAddress((void**)&a2, g_a2);
    cudaGetSymbolAddress((void**)&v,  g_v);

    const dim3 blk(256);
    auto eg = [](int M) { return dim3((unsigned)((M + 7) / 8)); };

    // a0 starts as x0 (residual fold). v starts zero (globals zeroed at init;
    // fmlp1 re-zeroes it every replay after fuse_a1 consumed it).
    cudaMemcpyAsync(a0, x0, (size_t)N0 * C * sizeof(float), cudaMemcpyDeviceToDevice, 0);

    // projections through the shared "inner" linear (bias deferred)
    run_tgemm(x0, WiW, y0, N0);
    run_tgemm(x1, WiW, y1, E1V);
    run_tgemm(x2, WiW, y2, E2V);

    // edge init of a1/a2 with residual x and folded linear biases
    edge_kernel<<<eg(E1V), blk>>>(y0, ei1, ei1 + E1V, Wib, x1, l111b, l211b, a1, E1V);
    edge_kernel<<<eg(E2V), blk>>>(y0, ei2, ei2 + E2V, Wib, x2, l222b, l211b, a2, E2V);
    scat_node_kernel<<<eg(E1V), blk>>>(y1, ei1, Wib, a0, E1V);
    scat_node_kernel<<<eg(E2V), blk>>>(y2, ei2, Wib, a0, E2V);

    // fused gather-GEMM-scatter aggregation passes
    // (1,1,1): a1[t0] += L111(relu(y1[t1]+y1[t2]+b))
    run_ggemm<false>(y1, y1, t111 + TV, t111 + 2 * TV, t111, Wib, l111W, a1, TV);
    // (2,2,2): a2[t0] += L222(relu(y2[t1]+y2[t2]+b))
    run_ggemm<false>(y2, y2, t222 + TV, t222 + 2 * TV, t222, Wib, l222W, a2, TV);
    // (1,1,2) part a: a2[t2] += L211(relu(y1[t0]+y1[t1]+b))
    run_ggemm<false>(y1, y1, t112, t112 + TV, t112 + 2 * TV, Wib, l211W, a2, TV);
    // (1,1,2) part b: v[t0] += L211(relu(y1[t1]+y2[t2]+b))   (f16 RED)
    run_ggemm<true>(y1, y2, t112 + TV, t112 + 2 * TV, t112, Wib, l211W, v, TV);
    fuse_a1_kernel<<<eg(E1V), blk>>>(a1, v, inv1, E1V);

    // fused output MLPs (a-buffers hold x + a + biases) + residual
    run_fmlp(a0, m0aW, m0ab, m0bW, m0bb, x0, out, nullptr, N0);
    run_fmlp(a1, m1aW, m1ab, m1bW, m1bb, x1, out + (size_t)N0 * C, v, E1V);
    run_fmlp(a2, m2aW, m2ab, m2bW, m2bb, x2, out + ((size_t)N0 + E1V) * C, nullptr, E2V);
}

// round 11
// speedup vs baseline: 1.4798x; 1.0374x over previous
#include <cuda_runtime.h>
#include <cuda_fp16.h>
#include <cstdint>
#include <cstddef>

#define C   128
#define N0  20000
#define E1V 500000
#define E2V 500000
#define TV  500000

// ---------------- static device scratch (no allocations allowed) ----------------
__device__ __half g_y0h[(size_t)N0 * C];
__device__ __half g_y1h[(size_t)E1V * C];
__device__ __half g_y2h[(size_t)E2V * C];
__device__ float  g_a0[(size_t)N0 * C];
__device__ float  g_a1[(size_t)E1V * C];
__device__ float  g_a2[(size_t)E2V * C];
__device__ __half g_v[(size_t)E1V * C];     // part-b linear output (f16, RED target)

__device__ __forceinline__ void red4(float* p, float a, float b, float c, float d) {
    asm volatile("red.global.add.v4.f32 [%0], {%1,%2,%3,%4};"
                 :: "l"(p), "f"(a), "f"(b), "f"(c), "f"(d) : "memory");
}
__device__ __forceinline__ void red2(float* p, float a, float b) {
    asm volatile("red.global.add.v2.f32 [%0], {%1,%2};"
                 :: "l"(p), "f"(a), "f"(b) : "memory");
}
__device__ __forceinline__ void redh1(__half* p, uint32_t v) {
    asm volatile("red.global.add.noftz.f16x2 [%0], %1;"
                 :: "l"(p), "r"(v) : "memory");
}
// pack two f32 -> f16x2
__device__ __forceinline__ uint32_t pk(float lo, float hi) {
    uint32_t d;
    asm("cvt.rn.f16x2.f32 %0, %1, %2;" : "=r"(d) : "f"(hi), "f"(lo));
    return d;
}
// two f16x2 words -> float4
__device__ __forceinline__ float4 two_words(uint32_t w0, uint32_t w1) {
    float2 a = __half22float2(*(__half2*)&w0);
    float2 b = __half22float2(*(__half2*)&w1);
    return make_float4(a.x, a.y, b.x, b.y);
}
// read 4 consecutive f16 of row as floats
__device__ __forceinline__ float4 ldy(const __half* y, int row, int lane) {
    uint2 u = *(const uint2*)(y + (size_t)row * C + lane * 4);
    return two_words(u.x, u.y);
}
// relu(ha + hb + bias) packed
__device__ __forceinline__ uint32_t gath_word(uint32_t ua, uint32_t ub, float2 bi) {
    float2 fa = __half22float2(*(__half2*)&ua);
    float2 fb = __half22float2(*(__half2*)&ub);
    return pk(fmaxf(fa.x + fb.x + bi.x, 0.f), fmaxf(fa.y + fb.y + bi.y, 0.f));
}

// ---- f16 tile layout: 128 rows, 8 k16-groups of 8 f16x2 words, row stride 72 ----
#define ROWW 72
#define TWORDS (128 * ROWW)
__device__ __forceinline__ int widx(int r, int g, int p) { return r * ROWW + g * 8 + p; }

// permute linear words [0..7] -> [0,4,1,5,2,6,3,7] per 8-word half
__device__ __forceinline__ void permute16(const uint32_t* lin, uint32_t* w) {
#pragma unroll
    for (int h = 0; h < 2; h++) {
        const uint32_t* i8 = lin + h * 8;
        uint32_t* o = w + h * 8;
        o[0] = i8[0]; o[1] = i8[4]; o[2] = i8[1]; o[3] = i8[5];
        o[4] = i8[2]; o[5] = i8[6]; o[6] = i8[3]; o[7] = i8[7];
    }
}

// LDG a 128x128 fp32 tile -> 16 packed f16x2 regs.
__device__ __forceinline__ void ldg_tile(const float* A, int row0, int M,
                                         int tid, uint32_t* w)
{
    const int row = row0 + (tid >> 2), q = tid & 3;
    uint32_t lin[16];
#pragma unroll
    for (int j = 0; j < 16; j++) lin[j] = 0;
    if (row < M) {
        const float4* g = (const float4*)(A + (size_t)row * C + q * 32);
#pragma unroll
        for (int j = 0; j < 8; j++) {
            float4 f = g[j];
            lin[j * 2 + 0] = pk(f.x, f.y);
            lin[j * 2 + 1] = pk(f.z, f.w);
        }
    }
    permute16(lin, w);
}

// Gathered A tile: row r = relu(ya[iA[r]] + yb[iB[r]] + binner), f16 sources.
__device__ __forceinline__ void ldg_gather(const __half* ya, const __half* yb,
                                           const int* iA, const int* iB,
                                           const float* binner, int row0, int M,
                                           int tid, uint32_t* w)
{
    const int r = row0 + (tid >> 2), q = tid & 3;
    uint32_t lin[16];
    if (r < M) {
        const int a = iA[r], b = iB[r];
        const uint4* ga = (const uint4*)(ya + (size_t)a * C + q * 32);
        const uint4* gb = (const uint4*)(yb + (size_t)b * C + q * 32);
        uint4 va[4], vb[4];
#pragma unroll
        for (int j = 0; j < 4; j++) { va[j] = ga[j]; vb[j] = gb[j]; }
        const float* bi = binner + q * 32;
#pragma unroll
        for (int j = 0; j < 4; j++) {
            float2 b0 = *(const float2*)(bi + j * 8 + 0);
            float2 b1 = *(const float2*)(bi + j * 8 + 2);
            float2 b2 = *(const float2*)(bi + j * 8 + 4);
            float2 b3 = *(const float2*)(bi + j * 8 + 6);
            lin[j * 4 + 0] = gath_word(va[j].x, vb[j].x, b0);
            lin[j * 4 + 1] = gath_word(va[j].y, vb[j].y, b1);
            lin[j * 4 + 2] = gath_word(va[j].z, vb[j].z, b2);
            lin[j * 4 + 3] = gath_word(va[j].w, vb[j].w, b3);
        }
    } else {
#pragma unroll
        for (int j = 0; j < 16; j++) lin[j] = 0;
    }
    permute16(lin, w);
}

__device__ __forceinline__ void sts_tile(uint32_t* buf, int tid, const uint32_t* w)
{
    const int row = tid >> 2, q = tid & 3;
    *(uint4*)(buf + widx(row, 2 * q,     0)) = make_uint4(w[0],  w[1],  w[2],  w[3]);
    *(uint4*)(buf + widx(row, 2 * q,     4)) = make_uint4(w[4],  w[5],  w[6],  w[7]);
    *(uint4*)(buf + widx(row, 2 * q + 1, 0)) = make_uint4(w[8],  w[9],  w[10], w[11]);
    *(uint4*)(buf + widx(row, 2 * q + 1, 4)) = make_uint4(w[12], w[13], w[14], w[15]);
}

__device__ __forceinline__ void mma_f16(const uint32_t* Ab, const uint32_t* Wb,
                                        int wm, int wn, int gid, int tig,
                                        float acc[2][4][4])
{
#pragma unroll
    for (int g = 0; g < 8; g++) {
        uint32_t af[2][4], bf[4][2];
#pragma unroll
        for (int t = 0; t < 2; t++) {
            const int rl = wm + t * 16 + gid;
            uint2 lo = *(const uint2*)(Ab + widx(rl,     g, tig * 2));
            uint2 hi = *(const uint2*)(Ab + widx(rl + 8, g, tig * 2));
            af[t][0] = lo.x; af[t][1] = hi.x; af[t][2] = lo.y; af[t][3] = hi.y;
        }
#pragma unroll
        for (int tb = 0; tb < 4; tb++) {
            const int n = wn + tb * 8 + gid;
            uint2 b = *(const uint2*)(Wb + widx(n, g, tig * 2));
            bf[tb][0] = b.x; bf[tb][1] = b.y;
        }
#pragma unroll
        for (int t = 0; t < 2; t++)
#pragma unroll
            for (int tb = 0; tb < 4; tb++)
                asm("mma.sync.aligned.m16n8k16.row.col.f32.f16.f16.f32 "
                    "{%0,%1,%2,%3}, {%4,%5,%6,%7}, {%8,%9}, {%0,%1,%2,%3};"
                    : "+f"(acc[t][tb][0]), "+f"(acc[t][tb][1]),
                      "+f"(acc[t][tb][2]), "+f"(acc[t][tb][3])
                    : "r"(af[t][0]), "r"(af[t][1]), "r"(af[t][2]), "r"(af[t][3]),
                      "r"(bf[tb][0]), "r"(bf[tb][1]));
    }
}

#define GEMM_SMEM (3 * TWORDS * 4)

// ===== projection GEMM: y(half) = A(f32) @ W^T ; optional fused node-scatter =====
// SCAT: a0scat[sidx[r]] += relu(y[r] + bscat)  (a0 is L2-resident, red2 fp32)
template<bool SCAT>
__global__ __launch_bounds__(512, 1)
void tgemm(const float* __restrict__ A, const float* __restrict__ W,
           __half* __restrict__ Cout, const int* __restrict__ sidx,
           const float* __restrict__ bscat, float* __restrict__ a0scat,
           int M, int ntiles)
{
    extern __shared__ uint32_t sm[];
    uint32_t* Wf = sm;
    uint32_t* Ab[2] = { sm + TWORDS, sm + 2 * TWORDS };
    const int tid = threadIdx.x;
    const int lane = tid & 31, warp = tid >> 5;
    const int gid = lane >> 2, tig = lane & 3;
    const int wm = (warp >> 2) * 32, wn = (warp & 3) * 32;

    uint32_t w[16];
    int tile = blockIdx.x;
    { uint32_t ww[16]; ldg_tile(W, 0, 128, tid, ww); sts_tile(Wf, tid, ww); }
    if (tile < ntiles) { ldg_tile(A, tile * 128, M, tid, w); sts_tile(Ab[0], tid, w); }
    __syncthreads();

    int buf = 0;
    for (; tile < ntiles; tile += gridDim.x) {
        const int nxt = tile + gridDim.x;
        const bool hn = nxt < ntiles;
        if (hn) ldg_tile(A, nxt * 128, M, tid, w);

        float acc[2][4][4];
#pragma unroll
        for (int t = 0; t < 2; t++)
#pragma unroll
            for (int tb = 0; tb < 4; tb++)
#pragma unroll
                for (int i = 0; i < 4; i++) acc[t][tb][i] = 0.f;
        mma_f16(Ab[buf], Wf, wm, wn, gid, tig, acc);

        if (hn) sts_tile(Ab[buf ^ 1], tid, w);
#pragma unroll
        for (int t = 0; t < 2; t++) {
            const int r = tile * 128 + wm + t * 16 + gid;
            int d0 = 0, d1 = 0;
            if (SCAT) {
                if (r < M)     d0 = sidx[r];
                if (r + 8 < M) d1 = sidx[r + 8];
            }
#pragma unroll
            for (int tb = 0; tb < 4; tb++) {
                const int cc = wn + tb * 8 + tig * 2;
                float2 bs;
                if (SCAT) bs = *(const float2*)(bscat + cc);
                if (r < M) {
                    *(uint32_t*)(Cout + (size_t)r * C + cc) =
                        pk(acc[t][tb][0], acc[t][tb][1]);
                    if (SCAT)
                        red2(a0scat + (size_t)d0 * C + cc,
                             fmaxf(acc[t][tb][0] + bs.x, 0.f),
                             fmaxf(acc[t][tb][1] + bs.y, 0.f));
                }
                if (r + 8 < M) {
                    *(uint32_t*)(Cout + (size_t)(r + 8) * C + cc) =
                        pk(acc[t][tb][2], acc[t][tb][3]);
                    if (SCAT)
                        red2(a0scat + (size_t)d1 * C + cc,
                             fmaxf(acc[t][tb][2] + bs.x, 0.f),
                             fmaxf(acc[t][tb][3] + bs.y, 0.f));
                }
            }
        }
        __syncthreads();
        buf ^= 1;
    }
}

// ============ gather-GEMM-scatter: dst[iD[r]] += relu(ya[iA]+yb[iB]+bi) @ W^T ====
template<bool OUTH>
__global__ __launch_bounds__(512, 1)
void ggemm(const __half* __restrict__ ya, const __half* __restrict__ yb,
           const int* __restrict__ iA, const int* __restrict__ iB,
           const int* __restrict__ iD, const float* __restrict__ binner,
           const float* __restrict__ W, void* __restrict__ dst, int M, int ntiles)
{
    extern __shared__ uint32_t sm[];
    uint32_t* Wf = sm;
    uint32_t* Ab[2] = { sm + TWORDS, sm + 2 * TWORDS };
    const int tid = threadIdx.x;
    const int lane = tid & 31, warp = tid >> 5;
    const int gid = lane >> 2, tig = lane & 3;
    const int wm = (warp >> 2) * 32, wn = (warp & 3) * 32;

    uint32_t w[16];
    int tile = blockIdx.x;
    { uint32_t ww[16]; ldg_tile(W, 0, 128, tid, ww); sts_tile(Wf, tid, ww); }
    if (tile < ntiles) {
        ldg_gather(ya, yb, iA, iB, binner, tile * 128, M, tid, w);
        sts_tile(Ab[0], tid, w);
    }
    __syncthreads();

    int buf = 0;
    for (; tile < ntiles; tile += gridDim.x) {
        const int nxt = tile + gridDim.x;
        const bool hn = nxt < ntiles;
        if (hn) ldg_gather(ya, yb, iA, iB, binner, nxt * 128, M, tid, w);

        float acc[2][4][4];
#pragma unroll
        for (int t = 0; t < 2; t++)
#pragma unroll
            for (int tb = 0; tb < 4; tb++)
#pragma unroll
                for (int i = 0; i < 4; i++) acc[t][tb][i] = 0.f;
        mma_f16(Ab[buf], Wf, wm, wn, gid, tig, acc);

        if (hn) sts_tile(Ab[buf ^ 1], tid, w);

#pragma unroll
        for (int t = 0; t < 2; t++) {
            const int r = tile * 128 + wm + t * 16 + gid;
            if (r < M) {
                const size_t base = (size_t)iD[r] * C;
#pragma unroll
                for (int tb = 0; tb < 4; tb++) {
                    const int cc = wn + tb * 8 + tig * 2;
                    if (OUTH)
                        redh1((__half*)dst + base + cc, pk(acc[t][tb][0], acc[t][tb][1]));
                    else
                        red2((float*)dst + base + cc, acc[t][tb][0], acc[t][tb][1]);
                }
            }
            if (r + 8 < M) {
                const size_t base = (size_t)iD[r + 8] * C;
#pragma unroll
                for (int tb = 0; tb < 4; tb++) {
                    const int cc = wn + tb * 8 + tig * 2;
                    if (OUTH)
                        redh1((__half*)dst + base + cc, pk(acc[t][tb][2], acc[t][tb][3]));
                    else
                        red2((float*)dst + base + cc, acc[t][tb][2], acc[t][tb][3]);
                }
            }
        }
        __syncthreads();
        buf ^= 1;
    }
}

// ======================= fused 2-layer MLP (f16) =================================
// out = relu(Ain@Wa^T + ba) @ Wb^T + bb + R
// WITHV: Ain[r] = A[r] + v[r] + v[inv1[r]]  (v f16)
// zp: zero zp rows while streaming (restores v for the next replay)
#define FMLP_SMEM (4 * TWORDS * 4)
template<bool WITHV>
__global__ __launch_bounds__(512, 1)
void fmlp(const float* __restrict__ A, const float* __restrict__ Wa,
          const float* __restrict__ ba, const float* __restrict__ Wb,
          const float* __restrict__ bb, const float* __restrict__ R,
          float* __restrict__ out, const __half* __restrict__ v,
          const int* __restrict__ inv1, __half* __restrict__ zp, int M, int ntiles)
{
    extern __shared__ uint32_t sm[];
    uint32_t* Wfa = sm;
    uint32_t* Wfb = sm + TWORDS;
    uint32_t* Ab[2] = { sm + 2 * TWORDS, sm + 3 * TWORDS };
    const int tid = threadIdx.x;
    const int lane = tid & 31, warp = tid >> 5;
    const int gid = lane >> 2, tig = lane & 3;
    const int wm = (warp >> 2) * 32, wn = (warp & 3) * 32;
    const int lrow = tid >> 2, q = tid & 3;

    auto ld = [&](int row0, uint32_t* dst) {
        const int r = row0 + lrow;
        uint32_t lin[16];
#pragma unroll
        for (int j = 0; j < 16; j++) lin[j] = 0;
        if (r < M) {
            float4 f[8];
            const float4* g = (const float4*)(A + (size_t)r * C + q * 32);
#pragma unroll
            for (int j = 0; j < 8; j++) f[j] = g[j];
            if (WITHV) {
                const int gi = inv1[r];
                const uint4* gv = (const uint4*)(v + (size_t)r * C + q * 32);
                const uint4* gg = (const uint4*)(v + (size_t)gi * C + q * 32);
#pragma unroll
                for (int j = 0; j < 4; j++) {
                    uint4 av = gv[j], ag = gg[j];
                    float4 s0 = two_words(av.x, av.y), s1 = two_words(av.z, av.w);
                    float4 t0 = two_words(ag.x, ag.y), t1 = two_words(ag.z, ag.w);
                    f[2 * j].x     += s0.x + t0.x; f[2 * j].y     += s0.y + t0.y;
                    f[2 * j].z     += s0.z + t0.z; f[2 * j].w     += s0.w + t0.w;
                    f[2 * j + 1].x += s1.x + t1.x; f[2 * j + 1].y += s1.y + t1.y;
                    f[2 * j + 1].z += s1.z + t1.z; f[2 * j + 1].w += s1.w + t1.w;
                }
            }
#pragma unroll
            for (int j = 0; j < 8; j++) {
                lin[j * 2 + 0] = pk(f[j].x, f[j].y);
                lin[j * 2 + 1] = pk(f[j].z, f[j].w);
            }
            if (zp) {
                uint4* z = (uint4*)(zp + (size_t)r * C + q * 32);
#pragma unroll
                for (int j = 0; j < 4; j++) z[j] = make_uint4(0, 0, 0, 0);
            }
        }
        permute16(lin, dst);
    };

    uint32_t w[16];
    int tile = blockIdx.x;
    { uint32_t ww[16]; ldg_tile(Wa, 0, 128, tid, ww); sts_tile(Wfa, tid, ww); }
    { uint32_t ww[16]; ldg_tile(Wb, 0, 128, tid, ww); sts_tile(Wfb, tid, ww); }
    if (tile < ntiles) { ld(tile * 128, w); sts_tile(Ab[0], tid, w); }
    __syncthreads();

    int buf = 0;
    for (; tile < ntiles; tile += gridDim.x) {
        const int nxt = tile + gridDim.x;
        const bool hn = nxt < ntiles;
        if (hn) ld(nxt * 128, w);

        float acc[2][4][4];
#pragma unroll
        for (int t = 0; t < 2; t++)
#pragma unroll
            for (int tb = 0; tb < 4; tb++)
#pragma unroll
                for (int i = 0; i < 4; i++) acc[t][tb][i] = 0.f;
        mma_f16(Ab[buf], Wfa, wm, wn, gid, tig, acc);
        __syncthreads();

        {   // hidden = relu(acc + ba) -> back into Ab[buf]
            const int gbase = wn >> 4;
#pragma unroll
            for (int t = 0; t < 2; t++) {
                const int rl = wm + t * 16 + gid;
#pragma unroll
                for (int tb = 0; tb < 4; tb++) {
                    const int cc = wn + tb * 8 + tig * 2;
                    const int g = gbase + (tb >> 1);
                    const int p = 2 * tig + (tb & 1);
                    float2 b2 = *(const float2*)(ba + cc);
                    Ab[buf][widx(rl,     g, p)] = pk(fmaxf(acc[t][tb][0] + b2.x, 0.f),
                                                     fmaxf(acc[t][tb][1] + b2.y, 0.f));
                    Ab[buf][widx(rl + 8, g, p)] = pk(fmaxf(acc[t][tb][2] + b2.x, 0.f),
                                                     fmaxf(acc[t][tb][3] + b2.y, 0.f));
                }
            }
        }
        __syncthreads();

#pragma unroll
        for (int t = 0; t < 2; t++)
#pragma unroll
            for (int tb = 0; tb < 4; tb++)
#pragma unroll
                for (int i = 0; i < 4; i++) acc[t][tb][i] = 0.f;
        mma_f16(Ab[buf], Wfb, wm, wn, gid, tig, acc);

        if (hn) sts_tile(Ab[buf ^ 1], tid, w);
#pragma unroll
        for (int t = 0; t < 2; t++) {
            const int r = tile * 128 + wm + t * 16 + gid;
#pragma unroll
            for (int tb = 0; tb < 4; tb++) {
                const int cc = wn + tb * 8 + tig * 2;
                float2 bb2 = *(const float2*)(bb + cc);
                if (r < M) {
                    float2 o = *(const float2*)(R + (size_t)r * C + cc);
                    *(float2*)(out + (size_t)r * C + cc) =
                        make_float2(acc[t][tb][0] + bb2.x + o.x,
                                    acc[t][tb][1] + bb2.y + o.y);
                }
                if (r + 8 < M) {
                    float2 o = *(const float2*)(R + (size_t)(r + 8) * C + cc);
                    *(float2*)(out + (size_t)(r + 8) * C + cc) =
                        make_float2(acc[t][tb][2] + bb2.x + o.x,
                                    acc[t][tb][3] + bb2.y + o.y);
                }
            }
        }
        __syncthreads();
        buf ^= 1;
    }
}

// ---- edge: dst[r] = relu(y[s]+y[e]+bi) + x[r] + b1 + b2 -------------------------
__global__ void edge_kernel(const __half* __restrict__ y, const int* __restrict__ s,
                            const int* __restrict__ e, const float* __restrict__ bi,
                            const float* __restrict__ x, const float* __restrict__ b1,
                            const float* __restrict__ b2, float* __restrict__ dst, int M)
{
    const int w = (blockIdx.x * blockDim.x + threadIdx.x) >> 5;
    const int lane = threadIdx.x & 31;
    if (w >= M) return;
    float4 va = ldy(y, s[w], lane);
    float4 vb = ldy(y, e[w], lane);
    float4 bb = *(const float4*)(bi + lane * 4);
    float4 c1 = *(const float4*)(b1 + lane * 4);
    float4 c2 = *(const float4*)(b2 + lane * 4);
    float4 xx = *(const float4*)(x + (size_t)w * C + lane * 4);
    float4 o;
    o.x = fmaxf(va.x + vb.x + bb.x, 0.f) + xx.x + c1.x + c2.x;
    o.y = fmaxf(va.y + vb.y + bb.y, 0.f) + xx.y + c1.y + c2.y;
    o.z = fmaxf(va.z + vb.z + bb.z, 0.f) + xx.z + c1.z + c2.z;
    o.w = fmaxf(va.w + vb.w + bb.w, 0.f) + xx.w + c1.w + c2.w;
    *(float4*)(dst + (size_t)w * C + lane * 4) = o;
}

// ================================================================================
template<bool SCAT>
static inline void run_tgemm(const float* A, const float* W, __half* Co,
                             const int* sidx, const float* bscat, float* a0, int M)
{
    int nt = (M + 127) / 128;
    int grid = nt < 148 ? nt : 148;
    cudaFuncSetAttribute(tgemm<SCAT>, cudaFuncAttributeMaxDynamicSharedMemorySize, GEMM_SMEM);
    tgemm<SCAT><<<grid, 512, GEMM_SMEM>>>(A, W, Co, sidx, bscat, a0, M, nt);
}

template<bool OUTH>
static inline void run_ggemm(const __half* ya, const __half* yb, const int* iA,
                             const int* iB, const int* iD, const float* bi,
                             const float* W, void* dst, int M)
{
    int nt = (M + 127) / 128;
    int grid = nt < 148 ? nt : 148;
    cudaFuncSetAttribute(ggemm<OUTH>, cudaFuncAttributeMaxDynamicSharedMemorySize, GEMM_SMEM);
    ggemm<OUTH><<<grid, 512, GEMM_SMEM>>>(ya, yb, iA, iB, iD, bi, W, dst, M, nt);
}

template<bool WITHV>
static inline void run_fmlp(const float* A, const float* Wa, const float* ba,
                            const float* Wb, const float* bb, const float* R,
                            float* out, const __half* v, const int* inv1,
                            __half* zp, int M)
{
    int nt = (M + 127) / 128;
    int grid = nt < 148 ? nt : 148;
    cudaFuncSetAttribute(fmlp<WITHV>, cudaFuncAttributeMaxDynamicSharedMemorySize, FMLP_SMEM);
    fmlp<WITHV><<<grid, 512, FMLP_SMEM>>>(A, Wa, ba, Wb, bb, R, out, v, inv1, zp, M, nt);
}

extern "C" void kernel_launch(void* const* d_in, const int* in_sizes, int n_in,
                              void* d_out, int out_size)
{
    (void)in_sizes; (void)n_in; (void)out_size;
    const float* x0   = (const float*)d_in[0];
    const float* x1   = (const float*)d_in[1];
    const float* x2   = (const float*)d_in[2];
    const int*   ei1  = (const int*)d_in[3];
    const int*   ei2  = (const int*)d_in[4];
    const int*   t111 = (const int*)d_in[5];
    const int*   t222 = (const int*)d_in[6];
    const int*   t112 = (const int*)d_in[7];
    const int*   inv1 = (const int*)d_in[8];
    const float* WiW  = (const float*)d_in[10]; const float* Wib  = (const float*)d_in[11];
    const float* l111W= (const float*)d_in[12]; const float* l111b= (const float*)d_in[13];
    const float* l222W= (const float*)d_in[14]; const float* l222b= (const float*)d_in[15];
    const float* l211W= (const float*)d_in[16]; const float* l211b= (const float*)d_in[17];
    const float* m0aW = (const float*)d_in[18]; const float* m0ab = (const float*)d_in[19];
    const float* m0bW = (const float*)d_in[20]; const float* m0bb = (const float*)d_in[21];
    const float* m1aW = (const float*)d_in[22]; const float* m1ab = (const float*)d_in[23];
    const float* m1bW = (const float*)d_in[24]; const float* m1bb = (const float*)d_in[25];
    const float* m2aW = (const float*)d_in[26]; const float* m2ab = (const float*)d_in[27];
    const float* m2bW = (const float*)d_in[28]; const float* m2bb = (const float*)d_in[29];
    float* out = (float*)d_out;

    __half *y0, *y1, *y2, *v;
    float *a0, *a1, *a2;
    cudaGetSymbolAddress((void**)&y0, g_y0h);
    cudaGetSymbolAddress((void**)&y1, g_y1h);
    cudaGetSymbolAddress((void**)&y2, g_y2h);
    cudaGetSymbolAddress((void**)&a0, g_a0);
    cudaGetSymbolAddress((void**)&a1, g_a1);
    cudaGetSymbolAddress((void**)&a2, g_a2);
    cudaGetSymbolAddress((void**)&v,  g_v);

    const dim3 blk(256);
    auto eg = [](int M) { return dim3((unsigned)((M + 7) / 8)); };

    // a0 starts as x0 (residual fold). v starts zero (globals zeroed at init;
    // fmlp2 re-zeroes it every replay after fmlp1 consumed it).
    cudaMemcpyAsync(a0, x0, (size_t)N0 * C * sizeof(float), cudaMemcpyDeviceToDevice, 0);

    // projections; x1/x2 projections fuse the node scatter into a0 (L2-resident)
    run_tgemm<false>(x0, WiW, y0, nullptr, nullptr, nullptr, N0);           // 1
    run_tgemm<true >(x1, WiW, y1, ei1, Wib, a0, E1V);                       // 2
    run_tgemm<true >(x2, WiW, y2, ei2, Wib, a0, E2V);                       // 3

    // edge init of a1/a2 with residual x and folded linear biases
    edge_kernel<<<eg(E1V), blk>>>(y0, ei1, ei1 + E1V, Wib, x1, l111b, l211b, a1, E1V); // 4
    edge_kernel<<<eg(E2V), blk>>>(y0, ei2, ei2 + E2V, Wib, x2, l222b, l211b, a2, E2V); // 5

    // fused gather-GEMM-scatter aggregation passes
    // (1,1,1): a1[t0] += L111(relu(y1[t1]+y1[t2]+b))        <- ncu slot 6
    run_ggemm<false>(y1, y1, t111 + TV, t111 + 2 * TV, t111, Wib, l111W, a1, TV);
    // (2,2,2): a2[t0] += L222(relu(y2[t1]+y2[t2]+b))
    run_ggemm<false>(y2, y2, t222 + TV, t222 + 2 * TV, t222, Wib, l222W, a2, TV);
    // (1,1,2) part a: a2[t2] += L211(relu(y1[t0]+y1[t1]+b))
    run_ggemm<false>(y1, y1, t112, t112 + TV, t112 + 2 * TV, Wib, l211W, a2, TV);
    // (1,1,2) part b: v[t0] += L211(relu(y1[t1]+y2[t2]+b))   (f16 RED)
    run_ggemm<true>(y1, y2, t112 + TV, t112 + 2 * TV, t112, Wib, l211W, v, TV);

    // fused output MLPs + residual; fmlp1 folds v + v[inv1]; fmlp2 re-zeroes v
    run_fmlp<false>(a0, m0aW, m0ab, m0bW, m0bb, x0, out, nullptr, nullptr, nullptr, N0);
    run_fmlp<true >(a1, m1aW, m1ab, m1bW, m1bb, x1, out + (size_t)N0 * C,
                    v, inv1, nullptr, E1V);
    run_fmlp<false>(a2, m2aW, m2ab, m2bW, m2bb, x2, out + ((size_t)N0 + E1V) * C,
                    nullptr, nullptr, v, E2V);
}